// round 4
// baseline (speedup 1.0000x reference)
#include <cuda_runtime.h>

#define BB      16
#define HH      32
#define DD      128
#define HIDDEN  4096      // HH*DD
#define MB      128
#define BSZ     16
#define SMAX    2048      // MB*BSZ
#define SPLITS  8
#define SPLIT_S (SMAX / SPLITS)   // 256
#define EPS     1e-6f
#define SCALE   0.08838834764831845f   // 1/sqrt(128)

// Persistent device scratch (zero-initialized at module load; counters are
// reset to 0 by the combining CTA every call -> graph-replay safe)
__device__ float g_pm[BB * HH * SPLITS];
__device__ float g_pl[BB * HH * SPLITS];
__device__ float g_po[BB * HH * SPLITS * DD];
__device__ int   g_cnt[BB * HH];

// ---------------------------------------------------------------------------
// Single fused kernel: RMSNorm (redundant per-CTA) + flash-decoding partial +
// last-CTA combine with residual.  grid = B*H*SPLITS = 4096, block = 256
// ---------------------------------------------------------------------------
__global__ void __launch_bounds__(256) attn_fused(
        const float* __restrict__ hidden,
        const float* __restrict__ kc,
        const float* __restrict__ vc,
        const int*   __restrict__ bt,
        const int*   __restrict__ ctx,
        const float* __restrict__ w,
        float*       __restrict__ out) {

    int idx   = blockIdx.x;
    int split = idx & (SPLITS - 1);
    int bh    = idx >> 3;
    int h     = bh & (HH - 1);
    int b     = bh >> 5;
    int tid   = threadIdx.x;
    int warp  = tid >> 5;
    int lane  = tid & 31;

    __shared__ float sc[SPLIT_S];        // 1 KB scores
    __shared__ float red[8];
    __shared__ int   tbl[SPLIT_S / BSZ];
    __shared__ float accs[8 * DD];       // 4 KB per-warp V partials
    __shared__ float4 qsm[DD / 4];       // 512 B q row
    __shared__ bool  isLast;

    int n_ctx = ctx[b];
    int start = split * SPLIT_S;
    int end   = min(n_ctx, start + SPLIT_S);

    if (end <= start) {
        // empty split: publish neutral partial
        if (tid == 0) { g_pm[idx] = -1e30f; g_pl[idx] = 0.f; }
    } else {
        // ---- RMSNorm (redundant per CTA; hidden row is L2-hot) ----
        const float4* hp = (const float4*)(hidden + (size_t)b * HIDDEN);
        float s = 0.f;
#pragma unroll
        for (int i = 0; i < 4; i++) {
            float4 v = hp[tid + i * 256];
            s += v.x * v.x + v.y * v.y + v.z * v.z + v.w * v.w;
        }
#pragma unroll
        for (int o = 16; o; o >>= 1) s += __shfl_xor_sync(0xffffffffu, s, o);
        if (lane == 0) red[warp] = s;
        if (tid < SPLIT_S / BSZ)
            tbl[tid] = bt[b * MB + (start >> 4) + tid];
        __syncthreads();
        float t = red[0];
#pragma unroll
        for (int i = 1; i < 8; i++) t += red[i];
        float inv = rsqrtf(t * (1.0f / HIDDEN) + EPS);

        // build q row (32 float4) in smem
        if (tid < 32) {
            float4 hv = hp[h * 32 + tid];
            float4 wv = ((const float4*)w)[h * 32 + tid];
            float4 q;
            q.x = hv.x * inv * wv.x;
            q.y = hv.y * inv * wv.y;
            q.z = hv.z * inv * wv.z;
            q.w = hv.w * inv * wv.w;
            qsm[tid] = q;
        }
        __syncthreads();

        float4 qv = qsm[lane];

        // ---- phase A: scores ----
        for (int s0 = start + warp * 4; s0 < end; s0 += 32) {
            int cnt = min(4, end - s0);
            float p[4];
#pragma unroll
            for (int j = 0; j < 4; j++) {
                p[j] = 0.f;
                if (j < cnt) {
                    int sp  = s0 + j;
                    int blk = tbl[(sp - start) >> 4];
                    const float4* kp =
                        (const float4*)(kc + ((((size_t)blk) * BSZ + (sp & 15)) * HH + h) * DD);
                    float4 kv = kp[lane];
                    p[j] = qv.x * kv.x + qv.y * kv.y + qv.z * kv.z + qv.w * kv.w;
                }
            }
#pragma unroll
            for (int j = 0; j < 4; j++) {
#pragma unroll
                for (int o = 16; o; o >>= 1)
                    p[j] += __shfl_xor_sync(0xffffffffu, p[j], o);
            }
            if (lane == 0) {
#pragma unroll
                for (int j = 0; j < 4; j++)
                    if (j < cnt) sc[s0 - start + j] = p[j] * SCALE;
            }
        }
        __syncthreads();

        int n = end - start;   // <= 256

        // ---- phase B: softmax over split ----
        float m = (tid < n) ? sc[tid] : -1e30f;
#pragma unroll
        for (int o = 16; o; o >>= 1) m = fmaxf(m, __shfl_xor_sync(0xffffffffu, m, o));
        if (lane == 0) red[warp] = m;
        __syncthreads();
        m = red[0];
#pragma unroll
        for (int i = 1; i < 8; i++) m = fmaxf(m, red[i]);
        __syncthreads();

        float l = 0.f;
        if (tid < n) {
            float e = __expf(sc[tid] - m);
            sc[tid] = e;
            l = e;
        }
#pragma unroll
        for (int o = 16; o; o >>= 1) l += __shfl_xor_sync(0xffffffffu, l, o);
        if (lane == 0) red[warp] = l;
        __syncthreads();

        // ---- phase C: V accumulation ----
        float4 acc = make_float4(0.f, 0.f, 0.f, 0.f);
        for (int s0 = start + warp * 4; s0 < end; s0 += 32) {
            int cnt = min(4, end - s0);
#pragma unroll
            for (int j = 0; j < 4; j++) {
                if (j < cnt) {
                    int sp  = s0 + j;
                    int blk = tbl[(sp - start) >> 4];
                    const float4* vp =
                        (const float4*)(vc + ((((size_t)blk) * BSZ + (sp & 15)) * HH + h) * DD);
                    float4 vv = vp[lane];
                    float  e  = sc[sp - start];
                    acc.x += e * vv.x;
                    acc.y += e * vv.y;
                    acc.z += e * vv.z;
                    acc.w += e * vv.w;
                }
            }
        }
        ((float4*)accs)[warp * 32 + lane] = acc;
        __syncthreads();

        if (tid < DD) {
            float a = 0.f;
#pragma unroll
            for (int g = 0; g < 8; g++) a += accs[g * DD + tid];
            g_po[(size_t)idx * DD + tid] = a;
        }
        if (tid == 0) {
            g_pm[idx] = m;
            float L = 0.f;
#pragma unroll
            for (int i = 0; i < 8; i++) L += red[i];
            g_pl[idx] = L;
        }
    }

    // ---- publish + last-CTA combine ----
    __threadfence();
    if (tid == 0)
        isLast = (atomicAdd(&g_cnt[bh], 1) == SPLITS - 1);
    __syncthreads();

    if (isLast) {
        if (tid < DD) {
            int d = tid;
            float ms[SPLITS], ls[SPLITS];
            float M = -1e30f;
#pragma unroll
            for (int i = 0; i < SPLITS; i++) {
                ms[i] = g_pm[bh * SPLITS + i];
                ls[i] = g_pl[bh * SPLITS + i];
                M = fmaxf(M, ms[i]);
            }
            float L = 0.f, A = 0.f;
#pragma unroll
            for (int i = 0; i < SPLITS; i++) {
                if (ls[i] > 0.f) {
                    float wgt = __expf(ms[i] - M);
                    L += ls[i] * wgt;
                    A += wgt * g_po[(size_t)(bh * SPLITS + i) * DD + d];
                }
            }
            int o = bh * DD + d;   // == b*HIDDEN + h*DD + d
            out[o] = hidden[o] + A / L;
        }
        if (tid == 0) g_cnt[bh] = 0;   // reset for next graph replay
    }
}

// ---------------------------------------------------------------------------
extern "C" void kernel_launch(void* const* d_in, const int* in_sizes, int n_in,
                              void* d_out, int out_size) {
    const float* hidden = (const float*)d_in[0];
    const float* kc     = (const float*)d_in[1];
    const float* vc     = (const float*)d_in[2];
    const int*   bt     = (const int*)  d_in[3];
    const int*   ctx    = (const int*)  d_in[4];
    const float* w      = (const float*)d_in[5];
    float*       out    = (float*)d_out;

    attn_fused<<<BB * HH * SPLITS, 256>>>(hidden, kc, vc, bt, ctx, w, out);
}

// round 5
// speedup vs baseline: 1.1347x; 1.1347x over previous
#include <cuda_runtime.h>

#define BB      16
#define HH      32
#define DD      128
#define HIDDEN  4096      // HH*DD
#define MB      128
#define BSZ     16
#define SMAX    2048      // MB*BSZ
#define SPLITS  8
#define SPLIT_S (SMAX / SPLITS)   // 256
#define EPS     1e-6f
#define SCALE   0.08838834764831845f   // 1/sqrt(128)

// Persistent device scratch (counters reset by combining CTA -> replay safe)
__device__ float g_q [BB * HIDDEN];
__device__ float g_pm[BB * HH * SPLITS];
__device__ float g_pl[BB * HH * SPLITS];
__device__ float g_po[BB * HH * SPLITS * DD];
__device__ int   g_cnt[BB * HH];

// ---------------------------------------------------------------------------
// Kernel 1: RMSNorm -> q.   grid = B*H = 512 (redundant sumsq per CTA, the
// hidden row is L2-hot), block = 256. Each CTA writes only its 128-elem slice.
// ---------------------------------------------------------------------------
__global__ void __launch_bounds__(256) rms_kernel(const float* __restrict__ x,
                                                  const float* __restrict__ w) {
    int bh  = blockIdx.x;
    int h   = bh & (HH - 1);
    int b   = bh >> 5;
    int tid = threadIdx.x;
    int warp = tid >> 5, lane = tid & 31;

    const float4* xp = (const float4*)(x + (size_t)b * HIDDEN);

    float s = 0.f;
#pragma unroll
    for (int i = 0; i < 4; i++) {
        float4 v = xp[tid + i * 256];
        s += v.x * v.x + v.y * v.y + v.z * v.z + v.w * v.w;
    }
    __shared__ float red[8];
#pragma unroll
    for (int o = 16; o; o >>= 1) s += __shfl_xor_sync(0xffffffffu, s, o);
    if (lane == 0) red[warp] = s;
    __syncthreads();
    float t = red[0];
#pragma unroll
    for (int i = 1; i < 8; i++) t += red[i];
    float inv = rsqrtf(t * (1.0f / HIDDEN) + EPS);

    if (tid < 32) {
        float4 hv = xp[h * 32 + tid];
        float4 wv = ((const float4*)w)[h * 32 + tid];
        float4 q;
        q.x = hv.x * inv * wv.x;
        q.y = hv.y * inv * wv.y;
        q.z = hv.z * inv * wv.z;
        q.w = hv.w * inv * wv.w;
        ((float4*)(g_q + (size_t)b * HIDDEN + h * DD))[tid] = q;
    }
}

// ---------------------------------------------------------------------------
// Kernel 2: flash-decoding partial + fused last-CTA combine.
// grid = B*H*SPLITS = 4096, block = 256.
// Each warp handles 8 positions per iteration (8 independent LDG.128 batched).
// ---------------------------------------------------------------------------
__global__ void __launch_bounds__(256) attn_partial(
        const float* __restrict__ hidden,
        const float* __restrict__ kc,
        const float* __restrict__ vc,
        const int*   __restrict__ bt,
        const int*   __restrict__ ctx,
        float*       __restrict__ out) {

    int idx   = blockIdx.x;
    int split = idx & (SPLITS - 1);
    int bh    = idx >> 3;
    int h     = bh & (HH - 1);
    int b     = bh >> 5;
    int tid   = threadIdx.x;
    int warp  = tid >> 5;
    int lane  = tid & 31;

    __shared__ float sc[SPLIT_S];        // scores / probs
    __shared__ int   sbase[SPLIT_S];     // per-position row offset (floats)
    __shared__ float red[8];
    __shared__ float accs[8 * DD];       // per-warp V partials (4 KB)
    __shared__ bool  isLast;

    int n_ctx = ctx[b];
    int start = split * SPLIT_S;
    int end   = min(n_ctx, start + SPLIT_S);
    int n     = end - start;             // may be <= 0

    if (n > 0) {
        // ---- prologue: per-position row offsets ----
        if (tid < n) {
            int s   = start + tid;
            int blk = __ldg(&bt[b * MB + (s >> 4)]);
            sbase[tid] = ((blk * BSZ + (s & 15)) * HH + h) * DD;
        }
        // q row for this (b,h): one float4 per lane
        float4 qv = ((const float4*)(g_q + (size_t)b * HIDDEN + h * DD))[lane];
        __syncthreads();

        // ---- phase A: scores = scale * (q . K[s]), 8 positions per warp ----
        for (int i0 = warp * 8; i0 < n; i0 += 64) {
            int cnt = min(8, n - i0);
            float p[8];
#pragma unroll
            for (int j = 0; j < 8; j++) {
                p[j] = 0.f;
                if (j < cnt) {
                    const float4* kp = (const float4*)(kc + sbase[i0 + j]);
                    float4 kv = kp[lane];
                    p[j] = qv.x * kv.x + qv.y * kv.y + qv.z * kv.z + qv.w * kv.w;
                }
            }
#pragma unroll
            for (int j = 0; j < 8; j++) {
#pragma unroll
                for (int o = 16; o; o >>= 1)
                    p[j] += __shfl_xor_sync(0xffffffffu, p[j], o);
            }
            if (lane == 0) {
#pragma unroll
                for (int j = 0; j < 8; j++)
                    if (j < cnt) sc[i0 + j] = p[j] * SCALE;
            }
        }
        __syncthreads();

        // ---- phase B: softmax over split (one element per thread) ----
        float m = (tid < n) ? sc[tid] : -1e30f;
#pragma unroll
        for (int o = 16; o; o >>= 1) m = fmaxf(m, __shfl_xor_sync(0xffffffffu, m, o));
        if (lane == 0) red[warp] = m;
        __syncthreads();
        m = red[0];
#pragma unroll
        for (int i = 1; i < 8; i++) m = fmaxf(m, red[i]);
        __syncthreads();

        float l = 0.f;
        if (tid < n) {
            float e = __expf(sc[tid] - m);
            sc[tid] = e;
            l = e;
        }
#pragma unroll
        for (int o = 16; o; o >>= 1) l += __shfl_xor_sync(0xffffffffu, l, o);
        if (lane == 0) red[warp] = l;
        __syncthreads();

        // ---- phase C: acc[d] += e_s * V[s][d], 8 positions per warp ----
        float4 acc = make_float4(0.f, 0.f, 0.f, 0.f);
        for (int i0 = warp * 8; i0 < n; i0 += 64) {
            int cnt = min(8, n - i0);
            float4 vv[8];
#pragma unroll
            for (int j = 0; j < 8; j++) {
                if (j < cnt)
                    vv[j] = ((const float4*)(vc + sbase[i0 + j]))[lane];
            }
#pragma unroll
            for (int j = 0; j < 8; j++) {
                if (j < cnt) {
                    float e = sc[i0 + j];
                    acc.x += e * vv[j].x;
                    acc.y += e * vv[j].y;
                    acc.z += e * vv[j].z;
                    acc.w += e * vv[j].w;
                }
            }
        }
        ((float4*)accs)[warp * 32 + lane] = acc;
        __syncthreads();

        if (tid < DD) {
            float a = 0.f;
#pragma unroll
            for (int g = 0; g < 8; g++) a += accs[g * DD + tid];
            g_po[(size_t)idx * DD + tid] = a;
        }
        if (tid == 0) {
            g_pm[idx] = m;
            float L = 0.f;
#pragma unroll
            for (int i = 0; i < 8; i++) L += red[i];
            g_pl[idx] = L;
        }
    } else {
        if (tid == 0) { g_pm[idx] = -1e30f; g_pl[idx] = 0.f; }
    }

    // ---- publish + last-CTA combine ----
    __threadfence();
    if (tid == 0)
        isLast = (atomicAdd(&g_cnt[bh], 1) == SPLITS - 1);
    __syncthreads();

    if (isLast) {
        __threadfence();   // acquire: make peers' partials visible
        if (tid < DD) {
            int d = tid;
            float ms[SPLITS], ls[SPLITS];
            float M = -1e30f;
#pragma unroll
            for (int i = 0; i < SPLITS; i++) {
                ms[i] = g_pm[bh * SPLITS + i];
                ls[i] = g_pl[bh * SPLITS + i];
                M = fmaxf(M, ms[i]);
            }
            float L = 0.f, A = 0.f;
#pragma unroll
            for (int i = 0; i < SPLITS; i++) {
                if (ls[i] > 0.f) {
                    float wgt = __expf(ms[i] - M);
                    L += ls[i] * wgt;
                    A += wgt * g_po[(size_t)(bh * SPLITS + i) * DD + d];
                }
            }
            int o = bh * DD + d;   // == b*HIDDEN + h*DD + d
            out[o] = hidden[o] + A / L;
        }
        if (tid == 0) g_cnt[bh] = 0;   // reset for next graph replay
    }
}

// ---------------------------------------------------------------------------
extern "C" void kernel_launch(void* const* d_in, const int* in_sizes, int n_in,
                              void* d_out, int out_size) {
    const float* hidden = (const float*)d_in[0];
    const float* kc     = (const float*)d_in[1];
    const float* vc     = (const float*)d_in[2];
    const int*   bt     = (const int*)  d_in[3];
    const int*   ctx    = (const int*)  d_in[4];
    const float* w      = (const float*)d_in[5];
    float*       out    = (float*)d_out;

    rms_kernel  <<<BB * HH,          256>>>(hidden, w);
    attn_partial<<<BB * HH * SPLITS, 256>>>(hidden, kc, vc, bt, ctx, out);
}

// round 6
// speedup vs baseline: 1.1414x; 1.0059x over previous
#include <cuda_runtime.h>

#define BB      16
#define HH      32
#define DD      128
#define HIDDEN  4096      // HH*DD
#define MB      128
#define BSZ     16
#define SMAX    2048      // MB*BSZ
#define SPLITS  8
#define SPLIT_S (SMAX / SPLITS)   // 256
#define EPS     1e-6f
#define SCALE   0.08838834764831845f   // 1/sqrt(128)

// Persistent device scratch (counters reset by combining CTA -> replay safe)
__device__ float g_q [BB * HIDDEN];
__device__ float g_pm[BB * HH * SPLITS];
__device__ float g_pl[BB * HH * SPLITS];
__device__ float g_po[BB * HH * SPLITS * DD];
__device__ int   g_cnt[BB * HH];

// ---------------------------------------------------------------------------
// Kernel 1: RMSNorm -> q.   grid = B*H = 512, block = 256.
// ---------------------------------------------------------------------------
__global__ void __launch_bounds__(256) rms_kernel(const float* __restrict__ x,
                                                  const float* __restrict__ w) {
    int bh  = blockIdx.x;
    int h   = bh & (HH - 1);
    int b   = bh >> 5;
    int tid = threadIdx.x;
    int warp = tid >> 5, lane = tid & 31;

    const float4* xp = (const float4*)(x + (size_t)b * HIDDEN);

    float s = 0.f;
#pragma unroll
    for (int i = 0; i < 4; i++) {
        float4 v = xp[tid + i * 256];
        s += v.x * v.x + v.y * v.y + v.z * v.z + v.w * v.w;
    }
    __shared__ float red[8];
#pragma unroll
    for (int o = 16; o; o >>= 1) s += __shfl_xor_sync(0xffffffffu, s, o);
    if (lane == 0) red[warp] = s;
    __syncthreads();
    float t = red[0];
#pragma unroll
    for (int i = 1; i < 8; i++) t += red[i];
    float inv = rsqrtf(t * (1.0f / HIDDEN) + EPS);

    if (tid < 32) {
        float4 hv = xp[h * 32 + tid];
        float4 wv = ((const float4*)w)[h * 32 + tid];
        float4 q;
        q.x = hv.x * inv * wv.x;
        q.y = hv.y * inv * wv.y;
        q.z = hv.z * inv * wv.z;
        q.w = hv.w * inv * wv.w;
        ((float4*)(g_q + (size_t)b * HIDDEN + h * DD))[tid] = q;
    }
}

// ---------------------------------------------------------------------------
// Kernel 2: single-pass online-softmax flash-decoding partial + fused combine.
// grid = B*H*SPLITS = 4096, block = 256.
// Per warp, per iteration: 8 V loads + 8 K loads in flight (online rescale).
// ---------------------------------------------------------------------------
__global__ void __launch_bounds__(256, 3) attn_partial(
        const float* __restrict__ hidden,
        const float* __restrict__ kc,
        const float* __restrict__ vc,
        const int*   __restrict__ bt,
        const int*   __restrict__ ctx,
        float*       __restrict__ out) {

    int idx   = blockIdx.x;
    int split = idx & (SPLITS - 1);
    int bh    = idx >> 3;
    int h     = bh & (HH - 1);
    int b     = bh >> 5;
    int tid   = threadIdx.x;
    int warp  = tid >> 5;
    int lane  = tid & 31;

    __shared__ int   sbase[SPLIT_S];     // per-position row offset (floats)
    __shared__ float red_m[8], red_l[8];
    __shared__ float accs[8 * DD];       // per-warp scaled V partials (4 KB)
    __shared__ bool  isLast;

    int n_ctx = ctx[b];
    int start = split * SPLIT_S;
    int end   = min(n_ctx, start + SPLIT_S);
    int n     = end - start;             // may be <= 0

    if (n > 0) {
        // ---- prologue: per-position row offsets ----
        if (tid < n) {
            int s   = start + tid;
            int blk = __ldg(&bt[b * MB + (s >> 4)]);
            sbase[tid] = ((blk * BSZ + (s & 15)) * HH + h) * DD;
        }
        float4 qv = ((const float4*)(g_q + (size_t)b * HIDDEN + h * DD))[lane];
        __syncthreads();

        // ---- single pass: online softmax, 8 positions per warp per iter ----
        float4 acc = make_float4(0.f, 0.f, 0.f, 0.f);
        float  mw  = -1e30f;
        float  lw  = 0.f;

        for (int i0 = warp * 8; i0 < n; i0 += 64) {
            int cnt = min(8, n - i0);

            // V loads first (longest to consume), then K loads + dots.
            float4 vv[8];
#pragma unroll
            for (int j = 0; j < 8; j++) {
                if (j < cnt)
                    vv[j] = ((const float4*)(vc + sbase[i0 + j]))[lane];
            }

            float p[8];
#pragma unroll
            for (int j = 0; j < 8; j++) {
                p[j] = 0.f;
                if (j < cnt) {
                    float4 kv = ((const float4*)(kc + sbase[i0 + j]))[lane];
                    p[j] = qv.x * kv.x + qv.y * kv.y + qv.z * kv.z + qv.w * kv.w;
                }
            }
            // all-lane butterfly sums -> every lane holds full scores
#pragma unroll
            for (int j = 0; j < 8; j++) {
#pragma unroll
                for (int o = 16; o; o >>= 1)
                    p[j] += __shfl_xor_sync(0xffffffffu, p[j], o);
            }
#pragma unroll
            for (int j = 0; j < 8; j++)
                p[j] = (j < cnt) ? p[j] * SCALE : -1e30f;

            float pm = p[0];
#pragma unroll
            for (int j = 1; j < 8; j++) pm = fmaxf(pm, p[j]);
            float newm = fmaxf(mw, pm);
            float r    = __expf(mw - newm);

            float e[8];
            float esum = 0.f;
#pragma unroll
            for (int j = 0; j < 8; j++) {
                e[j] = __expf(p[j] - newm);
                esum += e[j];
            }
            lw = lw * r + esum;

            acc.x *= r; acc.y *= r; acc.z *= r; acc.w *= r;
#pragma unroll
            for (int j = 0; j < 8; j++) {
                if (j < cnt) {
                    acc.x += e[j] * vv[j].x;
                    acc.y += e[j] * vv[j].y;
                    acc.z += e[j] * vv[j].z;
                    acc.w += e[j] * vv[j].w;
                }
            }
            mw = newm;
        }

        // ---- merge 8 warp states ----
        if (lane == 0) { red_m[warp] = mw; red_l[warp] = lw; }
        __syncthreads();

        float M = red_m[0];
#pragma unroll
        for (int i = 1; i < 8; i++) M = fmaxf(M, red_m[i]);
        float L = 0.f;
#pragma unroll
        for (int i = 0; i < 8; i++) L += red_l[i] * __expf(red_m[i] - M);

        float sw = __expf(mw - M);   // 0 for warps that saw no positions
        acc.x *= sw; acc.y *= sw; acc.z *= sw; acc.w *= sw;
        ((float4*)accs)[warp * 32 + lane] = acc;
        __syncthreads();

        if (tid < DD) {
            float a = 0.f;
#pragma unroll
            for (int g = 0; g < 8; g++) a += accs[g * DD + tid];
            g_po[(size_t)idx * DD + tid] = a;
        }
        if (tid == 0) {
            g_pm[idx] = M;
            g_pl[idx] = L;
        }
    } else {
        if (tid == 0) { g_pm[idx] = -1e30f; g_pl[idx] = 0.f; }
    }

    // ---- publish + last-CTA combine ----
    __threadfence();
    if (tid == 0)
        isLast = (atomicAdd(&g_cnt[bh], 1) == SPLITS - 1);
    __syncthreads();

    if (isLast) {
        __threadfence();   // acquire: make peers' partials visible
        if (tid < DD) {
            int d = tid;
            float ms[SPLITS], ls[SPLITS];
            float M = -1e30f;
#pragma unroll
            for (int i = 0; i < SPLITS; i++) {
                ms[i] = g_pm[bh * SPLITS + i];
                ls[i] = g_pl[bh * SPLITS + i];
                M = fmaxf(M, ms[i]);
            }
            float L = 0.f, A = 0.f;
#pragma unroll
            for (int i = 0; i < SPLITS; i++) {
                if (ls[i] > 0.f) {
                    float wgt = __expf(ms[i] - M);
                    L += ls[i] * wgt;
                    A += wgt * g_po[(size_t)(bh * SPLITS + i) * DD + d];
                }
            }
            int o = bh * DD + d;   // == b*HIDDEN + h*DD + d
            out[o] = hidden[o] + A / L;
        }
        if (tid == 0) g_cnt[bh] = 0;   // reset for next graph replay
    }
}

// ---------------------------------------------------------------------------
extern "C" void kernel_launch(void* const* d_in, const int* in_sizes, int n_in,
                              void* d_out, int out_size) {
    const float* hidden = (const float*)d_in[0];
    const float* kc     = (const float*)d_in[1];
    const float* vc     = (const float*)d_in[2];
    const int*   bt     = (const int*)  d_in[3];
    const int*   ctx    = (const int*)  d_in[4];
    const float* w      = (const float*)d_in[5];
    float*       out    = (float*)d_out;

    rms_kernel  <<<BB * HH,          256>>>(hidden, w);
    attn_partial<<<BB * HH * SPLITS, 256>>>(hidden, kc, vc, bt, ctx, out);
}